// round 13
// baseline (speedup 1.0000x reference)
#include <cuda_runtime.h>
#include <cuda_bf16.h>

// Fixed problem shape
#define Nn 128
#define Tt 1024
#define TM 512            // fwd owns t=0..511, bwd owns t=512..1023
#define Cc 256
#define Ll 128
#define NEGV    (-1e30f)
#define INV_LN2 1.4426950408889634f
#define LN2     0.6931471805599453f
#define NOTRDY  (1e30f)   // sentinel: real lp2/alpha/beta are all <= ~2
#define RSTG 16
#define BND  513          // boundary ring depth (slots 0..512, write-once)

__device__ float g_losses[Nn];

// ---------------------------------------------------------------------------
__device__ __forceinline__ float ex2f_(float x) {
    float y; asm("ex2.approx.ftz.f32 %0, %1;" : "=f"(y) : "f"(x)); return y;
}
__device__ __forceinline__ float lg2f_(float x) {
    float y; asm("lg2.approx.ftz.f32 %0, %1;" : "=f"(y) : "f"(x)); return y;
}
__device__ __forceinline__ float ld_acq_f(const float* p) {
    unsigned a = (unsigned)__cvta_generic_to_shared((const void*)p);
    int v; asm volatile("ld.acquire.cta.shared.b32 %0, [%1];"
                        : "=r"(v) : "r"(a) : "memory");
    return __int_as_float(v);
}
__device__ __forceinline__ void st_rel_f(float* p, float v) {
    unsigned a = (unsigned)__cvta_generic_to_shared((void*)p);
    asm volatile("st.release.cta.shared.b32 [%0], %1;"
                 :: "r"(a), "r"(__float_as_int(v)) : "memory");
}
__device__ __forceinline__ int ld_acq_i(const int* p) {
    unsigned a = (unsigned)__cvta_generic_to_shared((const void*)p);
    int v; asm volatile("ld.acquire.cta.shared.b32 %0, [%1];"
                        : "=r"(v) : "r"(a) : "memory");
    return v;
}
__device__ __forceinline__ void st_rel_i(int* p, int v) {
    unsigned a = (unsigned)__cvta_generic_to_shared((void*)p);
    asm volatile("st.release.cta.shared.b32 [%0], %1;"
                 :: "r"(a), "r"(v) : "memory");
}
__device__ __forceinline__ float pollf(const float* p) {
    float v = ld_acq_f(p);
    while (v > 1e29f) v = ld_acq_f(p);
    return v;
}
#define BARW() asm volatile("bar.sync 1, 128;" ::: "memory")   // fwd warps, once
#define BARC() asm volatile("bar.sync 3, 256;" ::: "memory")   // combine, once

// ---------------------------------------------------------------------------
// One block per batch element n. 512 threads (16 warps), NO per-step barrier:
//   warps  0-3 : forward alpha, register-resident (thread i: s=2i,2i+1;
//                thread 127: +s=256). Intra-warp halo by shfl_up; warp
//                boundaries via full-depth value-is-flag rings (skewed
//                wavefront, warp w+1 trails warp w).
//   warps  4-7 : backward beta (mirror; halo two values via shfl_down /
//                float2 boundary ring; warp 7 leads, warp 4 trails).
//   warps  8-11: fwd producers (stage row, base-2 lse, pre-gathered
//                emissions into glpF ring, blank lp2 flag in s_lpb[t]).
//   warps 12-15: bwd producers (rows descending from 1023).
// Combine at midpoint: loss = lse_s[ step(alpha_511)(s) + beta~_512(s) ].
// ---------------------------------------------------------------------------
__global__ void __launch_bounds__(512) ctc_fused(const float* __restrict__ preds,
                                                 const int*   __restrict__ targets) {
    __shared__ int   s_tg[Ll];
    __shared__ float s_lpb[Tt];                        // blank lp2 per t (flag)
    __shared__ __align__(16) float glpF[RSTG][Ll];     // ring: lp2 of tg[i]
    __shared__ __align__(16) float glpB[RSTG][Ll];
    __shared__ __align__(16) float rowF[4][Cc];
    __shared__ __align__(16) float rowB[4][Cc];
    __shared__ float  bndF[3][BND];                    // alpha_t[64w+63], flag
    __shared__ float2 bndB[3][BND];                    // beta_t[64w+64], [64w+65]
    __shared__ float  Bs[264];                         // beta~_512 dump
    __shared__ float  red[8];
    __shared__ int s_tdF, s_tdB;

    const int n    = blockIdx.x;
    const int tid  = threadIdx.x;
    const int wid  = tid >> 5;
    const int lane = tid & 31;
    const int grp  = tid >> 7;
    const size_t base = (size_t)n * Tt * Cc;

    int tgv = (tid < Ll) ? targets[n * Ll + tid] : 0;
    if (tid < Ll) s_tg[tid] = tgv;
    for (int k = tid; k < Tt; k += 512) s_lpb[k] = NOTRDY;
    for (int k = tid; k < 3 * BND; k += 512) (&bndF[0][0])[k] = NOTRDY;
    for (int k = tid; k < 3 * BND; k += 512) {
        (&bndB[0][0])[k].x = NOTRDY; (&bndB[0][0])[k].y = NOTRDY;
    }
    if (tid == 0) { s_tdF = -1; s_tdB = Tt; }
    const int tl = __syncthreads_count(tgv != 0);

    // ======================= producers =======================
    if (grp >= 2) {
        const bool fwd = (grp == 2);
        const int  w   = wid & 3;
        float* rbuf = fwd ? rowF[w] : rowB[w];
        const float4* p4 = (const float4*)(preds + base);
        int c0 = s_tg[4 * lane], c1 = s_tg[4 * lane + 1],
            c2 = s_tg[4 * lane + 2], c3 = s_tg[4 * lane + 3];

        int t0  = fwd ? w : (Tt - 1 - w);
        int stp = fwd ? 4 : -4;

        float4 f0 = __ldg(p4 + (size_t)t0 * 64 + lane);
        float4 f1 = __ldg(p4 + (size_t)t0 * 64 + lane + 32);
        float4 g0 = __ldg(p4 + (size_t)(t0 + stp) * 64 + lane);
        float4 g1 = __ldg(p4 + (size_t)(t0 + stp) * 64 + lane + 32);

        for (int t = t0; fwd ? (t < TM) : (t >= TM); t += stp) {
            int t2 = t + 2 * stp;
            float4 h0, h1;
            bool okp = fwd ? (t2 < TM) : (t2 >= TM);
            if (okp) {
                h0 = __ldg(p4 + (size_t)t2 * 64 + lane);
                h1 = __ldg(p4 + (size_t)t2 * 64 + lane + 32);
            }
            // backpressure vs SLOWEST consumer warp (13 < RSTG-2: race-free)
            if (fwd) { if (t >= RSTG)          while (ld_acq_i(&s_tdF) + 13 < t) { } }
            else     { if (t <= Tt - 1 - RSTG) while (ld_acq_i(&s_tdB) - 13 > t) { } }

            float4* dst = (float4*)rbuf;
            dst[lane] = f0; dst[lane + 32] = f1;
            __syncwarp();

            float S = ex2f_(f0.x * INV_LN2) + ex2f_(f0.y * INV_LN2)
                    + ex2f_(f0.z * INV_LN2) + ex2f_(f0.w * INV_LN2)
                    + ex2f_(f1.x * INV_LN2) + ex2f_(f1.y * INV_LN2)
                    + ex2f_(f1.z * INV_LN2) + ex2f_(f1.w * INV_LN2);
#pragma unroll
            for (int o = 16; o; o >>= 1) S += __shfl_xor_sync(0xffffffffu, S, o);
            float l2 = lg2f_(S);

            float4 q;
            q.x = __fmaf_rn(rbuf[c0], INV_LN2, -l2);
            q.y = __fmaf_rn(rbuf[c1], INV_LN2, -l2);
            q.z = __fmaf_rn(rbuf[c2], INV_LN2, -l2);
            q.w = __fmaf_rn(rbuf[c3], INV_LN2, -l2);
            float* grow = fwd ? glpF[t & (RSTG - 1)] : glpB[t & (RSTG - 1)];
            ((float4*)grow)[lane] = q;
            __syncwarp();
            if (lane == 0)
                st_rel_f(&s_lpb[t], __fmaf_rn(f0.x, INV_LN2, -l2));

            f0 = g0; f1 = g1; g0 = h0; g1 = h1;
        }
        return;
    }

    if (grp == 0) {
        // ======================= forward alpha (register wavefront) ==========
        const int i = tid, w = wid;
        int tg_i = s_tg[i];
        int tg_m = (i > 0) ? s_tg[i - 1] : 0;
        const bool sk   = tg_i && (tg_i != tg_m);
        const bool tail = (w == 3) && (lane == 31);     // owns s=256

        float a_even, a_odd, a256 = NEGV;
        // t = 0 init
        if (w == 0) {
            float lpB0 = pollf(&s_lpb[0]);
            float lpL0 = glpF[0][0];
            a_even = (lane == 0) ? lpB0 : NEGV;
            a_odd  = (lane == 0) ? lpL0 : NEGV;
        } else { a_even = NEGV; a_odd = NEGV; }
        if (lane == 31 && w < 3) st_rel_f(&bndF[w][0], a_odd);

        // 2-deep emission prefetch (per warp, independent)
        float lpB  = pollf(&s_lpb[1]);
        float lpL  = glpF[1][i];
        float lpBn = pollf(&s_lpb[2]);
        float lpLn = glpF[2][i];

        for (int t = 1; t < TM; ++t) {
            float h = __shfl_up_sync(0xffffffffu, a_odd, 1);
            if (lane == 0) h = (w == 0) ? NEGV : pollf(&bndF[w - 1][t - 1]);

            if (tail) {   // s=256 uses OLD a_odd (alpha_{t-1}[255])
                float mT = fmaxf(a256, a_odd);
                a256 = fmaxf(mT + lg2f_(ex2f_(a256 - mT) + ex2f_(a_odd - mT)) + lpB, NEGV);
            }
            float m  = fmaxf(fmaxf(a_even, a_odd), h);
            float ee = ex2f_(a_even - m);
            float eo = ex2f_(a_odd  - m);
            float eh = ex2f_(h      - m);
            float rE = m + lg2f_(ee + eh) + lpB;
            float rO = m + lg2f_(eo + ee + (sk ? eh : 0.f)) + lpL;
            a_even = fmaxf(rE, NEGV);
            a_odd  = fmaxf(rO, NEGV);

            if (lane == 31 && w < 3) st_rel_f(&bndF[w][t], a_odd);
            if (w == 3 && lane == 0) st_rel_i(&s_tdF, t);

            lpB = lpBn; lpL = lpLn;
            int tn = (t + 2 < TM) ? (t + 2) : (TM - 1);
            lpBn = pollf(&s_lpb[tn]);
            lpLn = glpF[tn & (RSTG - 1)][i];
        }

        BARC();   // beta~_512 ready in Bs

        // ---- combine: emission-free transition + dot + lse over s ----
        {
            float h = __shfl_up_sync(0xffffffffu, a_odd, 1);
            if (lane == 0) h = (w == 0) ? NEGV : pollf(&bndF[w - 1][TM - 1]);
            float2 B2 = ((const float2*)Bs)[i];

            float m  = fmaxf(fmaxf(a_even, a_odd), h);
            float ee = ex2f_(a_even - m);
            float eo = ex2f_(a_odd  - m);
            float eh = ex2f_(h      - m);
            float vE = m + lg2f_(ee + eh)                   + B2.x;
            float vO = m + lg2f_(eo + ee + (sk ? eh : 0.f)) + B2.y;

            float M = fmaxf(vE, vO);
            float E = ex2f_(vE - M) + ex2f_(vO - M);
            if (tail) {   // s'=256: stay a256 + step a255(=a_odd)
                float mT = fmaxf(a256, a_odd);
                float v256 = mT + lg2f_(ex2f_(a256 - mT) + ex2f_(a_odd - mT)) + Bs[256];
                float nm = fmaxf(M, v256);
                E = E * ex2f_(M - nm) + ex2f_(v256 - nm);
                M = nm;
            }
#pragma unroll
            for (int o = 16; o; o >>= 1) {
                float om = __shfl_xor_sync(0xffffffffu, M, o);
                float oe = __shfl_xor_sync(0xffffffffu, E, o);
                float nm = fmaxf(M, om);
                E = E * ex2f_(M - nm) + oe * ex2f_(om - nm);
                M = nm;
            }
            if (lane == 0) { red[2 * w] = M; red[2 * w + 1] = E; }
            BARW();
            if (tid == 0) {
                float Mf = red[0], Ef = red[1];
#pragma unroll
                for (int wv = 1; wv < 4; ++wv) {
                    float om = red[2 * wv], oe = red[2 * wv + 1];
                    float nm = fmaxf(Mf, om);
                    Ef = Ef * ex2f_(Mf - nm) + oe * ex2f_(om - nm);
                    Mf = nm;
                }
                float fin  = (Mf + lg2f_(Ef)) * LN2;
                float loss = (fin < -1e29f) ? 0.0f : -fin;   // zero_infinity
                int tld = (tl > 0) ? tl : 1;
                g_losses[n] = loss / (float)tld;
            }
        }
        return;
    }

    // ======================= backward beta (register wavefront) =============
    {
        const int j  = tid - 128;
        const int wb = wid - 4;
        int tgj  = s_tg[j];
        int tgj1 = (j + 1 < Ll) ? s_tg[j + 1] : 0;
        const bool skb  = tgj1 && (tgj1 != tgj);
        const bool tail = (wb == 3) && (lane == 31);    // j=127, owns s=256

        // t = 1023 init
        float lpB0 = pollf(&s_lpb[Tt - 1]);
        float lpO0 = glpB[(Tt - 1) & (RSTG - 1)][j];
        float b_even = (j == tl)     ? lpB0 : NEGV;     // s = 2j == 2tl
        float b_odd  = (j == tl - 1) ? lpO0 : NEGV;     // s = 2j+1 == 2tl-1
        float b256   = (tail && (tl == Ll || tl == 0)) ? lpB0 : NEGV;
        if (lane == 0 && wb > 0) {
            st_rel_f(&bndB[wb - 1][511].x, b_even);
            st_rel_f(&bndB[wb - 1][511].y, b_odd);
        }

        float lpB  = pollf(&s_lpb[Tt - 2]);
        float lpL  = glpB[(Tt - 2) & (RSTG - 1)][j];
        float lpBn = pollf(&s_lpb[Tt - 3]);
        float lpLn = glpB[(Tt - 3) & (RSTG - 1)][j];

        for (int t = Tt - 2; t >= TM; --t) {
            float h0 = __shfl_down_sync(0xffffffffu, b_even, 1);
            float h1 = __shfl_down_sync(0xffffffffu, b_odd, 1);
            if (lane == 31) {
                if (wb == 3) { h0 = b256; h1 = NEGV; }
                else {
                    int sl = (t + 1) - TM;
                    h0 = pollf(&bndB[wb][sl].x);
                    h1 = pollf(&bndB[wb][sl].y);
                }
            }
            if (tail) b256 = fmaxf(b256 + lpB, NEGV);   // s=256: self-loop only

            float bS = skb ? h1 : NEGV;
            float m  = fmaxf(fmaxf(b_even, b_odd), fmaxf(h0, bS));
            float e0 = ex2f_(b_even - m);
            float e1 = ex2f_(b_odd  - m);
            float e2 = ex2f_(h0     - m);
            float e3 = skb ? ex2f_(bS - m) : 0.f;
            float rE = m + lg2f_(e0 + e1)      + lpB;
            float rO = m + lg2f_(e1 + e2 + e3) + lpL;
            b_even = fmaxf(rE, NEGV);
            b_odd  = fmaxf(rO, NEGV);

            if (lane == 0 && wb > 0) {
                int sl = t - TM;
                st_rel_f(&bndB[wb - 1][sl].x, b_even);
                st_rel_f(&bndB[wb - 1][sl].y, b_odd);
            }
            if (wb == 0 && lane == 0) st_rel_i(&s_tdB, t);

            lpB = lpBn; lpL = lpLn;
            int tn = (t - 2 >= TM) ? (t - 2) : TM;
            lpBn = pollf(&s_lpb[tn]);
            lpLn = glpB[tn & (RSTG - 1)][j];
        }

        // publish beta~_512
        ((float2*)Bs)[j] = make_float2(b_even, b_odd);
        if (tail) Bs[256] = b256;
        BARC();
        return;
    }
}

// ---------------------------------------------------------------------------
__global__ void __launch_bounds__(128) reduce_kernel(float* __restrict__ out) {
    int tid = threadIdx.x;
    float v = g_losses[tid];
#pragma unroll
    for (int o = 16; o; o >>= 1) v += __shfl_xor_sync(0xffffffffu, v, o);
    __shared__ float sm[4];
    if ((tid & 31) == 0) sm[tid >> 5] = v;
    __syncthreads();
    if (tid == 0) out[0] = (sm[0] + sm[1] + sm[2] + sm[3]) * (1.0f / (float)Nn);
}

// ---------------------------------------------------------------------------
extern "C" void kernel_launch(void* const* d_in, const int* in_sizes, int n_in,
                              void* d_out, int out_size) {
    const float* preds;
    const int*   targets;
    if (in_sizes[0] == Nn * Tt * Cc) {
        preds   = (const float*)d_in[0];
        targets = (const int*)  d_in[1];
    } else {
        preds   = (const float*)d_in[1];
        targets = (const int*)  d_in[0];
    }
    float* out = (float*)d_out;

    ctc_fused   <<<Nn, 512>>>(preds, targets);
    reduce_kernel<<<1, 128>>>(out);
}

// round 15
// speedup vs baseline: 1.5179x; 1.5179x over previous
#include <cuda_runtime.h>
#include <cuda_bf16.h>

// Fixed problem shape
#define Nn 128
#define Tt 1024
#define TM 512            // fwd owns t=0..511, bwd owns t=512..1023
#define Cc 256
#define Ll 128
#define NEGV    (-1e30f)
#define INV_LN2 1.4426950408889634f
#define LN2     0.6931471805599453f
#define NOTRDY  (1e30f)
#define RSTG 16

__device__ float g_losses[Nn];

// ---------------------------------------------------------------------------
__device__ __forceinline__ float ex2f_(float x) {
    float y; asm("ex2.approx.ftz.f32 %0, %1;" : "=f"(y) : "f"(x)); return y;
}
__device__ __forceinline__ float lg2f_(float x) {
    float y; asm("lg2.approx.ftz.f32 %0, %1;" : "=f"(y) : "f"(x)); return y;
}
__device__ __forceinline__ float ld_acq_f(const float* p) {
    unsigned a = (unsigned)__cvta_generic_to_shared((const void*)p);
    int v; asm volatile("ld.acquire.cta.shared.b32 %0, [%1];"
                        : "=r"(v) : "r"(a) : "memory");
    return __int_as_float(v);
}
__device__ __forceinline__ void st_rel_f(float* p, float v) {
    unsigned a = (unsigned)__cvta_generic_to_shared((void*)p);
    asm volatile("st.release.cta.shared.b32 [%0], %1;"
                 :: "r"(a), "r"(__float_as_int(v)) : "memory");
}
__device__ __forceinline__ int ld_acq_i(const int* p) {
    unsigned a = (unsigned)__cvta_generic_to_shared((const void*)p);
    int v; asm volatile("ld.acquire.cta.shared.b32 %0, [%1];"
                        : "=r"(v) : "r"(a) : "memory");
    return v;
}
__device__ __forceinline__ void st_rel_i(int* p, int v) {
    unsigned a = (unsigned)__cvta_generic_to_shared((void*)p);
    asm volatile("st.release.cta.shared.b32 [%0], %1;"
                 :: "r"(a), "r"(v) : "memory");
}
__device__ __forceinline__ float pollf(const float* p) {
    float v = ld_acq_f(p);
    while (v > 1e29f) v = ld_acq_f(p);
    return v;
}
#define BARF() asm volatile("bar.sync 1, 128;" ::: "memory")
#define BARB() asm volatile("bar.sync 2, 128;" ::: "memory")
#define BARC() asm volatile("bar.sync 3, 256;" ::: "memory")

// forward pair: even s=2k (stay,step), odd s=2k+1 (stay,step,skip)
__device__ __forceinline__ float2 fpair(float aEm1, float aE0, float aO0,
                                        bool sk, float lpB, float lpL) {
    float m  = fmaxf(fmaxf(aE0, aEm1), aO0);
    float e0 = ex2f_(aE0 - m), e1 = ex2f_(aEm1 - m), e2 = ex2f_(aO0 - m);
    float rE = fmaxf(m + lg2f_(e0 + e1) + lpB, NEGV);
    float rO = fmaxf(m + lg2f_(e2 + e0 + (sk ? e1 : 0.f)) + lpL, NEGV);
    return make_float2(rE, rO);
}
// backward pair: even s=2k needs beta[2k,2k+1]; odd needs [2k+1,2k+2,(2k+3)]
__device__ __forceinline__ float2 bpair(float bE0, float bO0, float bE1, float bO1,
                                        bool skb, float lpB, float lpL) {
    float bS = skb ? bO1 : NEGV;
    float m  = fmaxf(fmaxf(bE0, bO0), fmaxf(bE1, bS));
    float e0 = ex2f_(bE0 - m), e1 = ex2f_(bO0 - m), e2 = ex2f_(bE1 - m);
    float e3 = skb ? ex2f_(bS - m) : 0.f;
    float rE = fmaxf(m + lg2f_(e0 + e1)      + lpB, NEGV);
    float rO = fmaxf(m + lg2f_(e1 + e2 + e3) + lpL, NEGV);
    return make_float2(rE, rO);
}

// ---------------------------------------------------------------------------
// One block per batch element n. 512 threads (16 warps):
//   warps 0-3 : forward alpha, DOUBLE-STEPPED: per barrier, thread i computes
//               pairs i-1,i at t+1 (redundant halo) then pair i at t+2 from
//               alpha_t in smem (k = s+4, 4 NEGV pads below). s=256 tail in a
//               register on thread 127.
//   warps 4-7 : backward beta, double-stepped mirror (pairs j,j+1 at t-1 then
//               pair j at t-2). beta[256] lives in smem (k=260), self-loop.
//   warps 8-11/12-15 : fwd/bwd producers (stage row, base-2 lse, pre-gathered
//               emissions into glp rings; blank lp2 flag in s_lpb[t]).
// Combine at midpoint: loss = lse_s[ step(alpha_511)(s) + beta~_512(s) ].
// ---------------------------------------------------------------------------
__global__ void __launch_bounds__(512) ctc_fused(const float* __restrict__ preds,
                                                 const int*   __restrict__ targets) {
    __shared__ int   s_tg[Ll];
    __shared__ float s_lpb[Tt];
    __shared__ __align__(16) float glpF[RSTG][Ll];
    __shared__ __align__(16) float glpB[RSTG][Ll];
    __shared__ __align__(16) float rowF[4][Cc];
    __shared__ __align__(16) float rowB[4][Cc];
    __shared__ __align__(16) float As[2][268];   // k = s+4; s=0..255 at k=4..259
    __shared__ __align__(16) float Bs[2][268];   // k = s+4; s=0..256 at k=4..260
    __shared__ float red[8];
    __shared__ int s_tdF, s_tdB;

    const int n    = blockIdx.x;
    const int tid  = threadIdx.x;
    const int wid  = tid >> 5;
    const int lane = tid & 31;
    const int grp  = tid >> 7;
    const size_t base = (size_t)n * Tt * Cc;

    int tgv = (tid < Ll) ? targets[n * Ll + tid] : 0;
    if (tid < Ll) s_tg[tid] = tgv;
    for (int k = tid; k < Tt; k += 512) s_lpb[k] = NOTRDY;
    if (tid < 4) {                                  // pads k=0..3
        As[0][tid] = NEGV; As[1][tid] = NEGV;
        Bs[0][tid] = NEGV; Bs[1][tid] = NEGV;
    }
    if (tid >= 4 && tid < 12) {                     // pads k=260..267
        As[0][256 + tid] = NEGV; As[1][256 + tid] = NEGV;
        if (tid >= 5) { Bs[0][256 + tid] = NEGV; Bs[1][256 + tid] = NEGV; } // 261..267
    }
    if (tid == 0) { s_tdF = -1; s_tdB = Tt; }
    const int tl = __syncthreads_count(tgv != 0);

    // ======================= producers =======================
    if (grp >= 2) {
        const bool fwd = (grp == 2);
        const int  w   = wid & 3;
        float* rbuf = fwd ? rowF[w] : rowB[w];
        const float4* p4 = (const float4*)(preds + base);
        int c0 = s_tg[4 * lane], c1 = s_tg[4 * lane + 1],
            c2 = s_tg[4 * lane + 2], c3 = s_tg[4 * lane + 3];

        int t0  = fwd ? w : (Tt - 1 - w);
        int stp = fwd ? 4 : -4;

        float4 f0 = __ldg(p4 + (size_t)t0 * 64 + lane);
        float4 f1 = __ldg(p4 + (size_t)t0 * 64 + lane + 32);
        float4 g0 = __ldg(p4 + (size_t)(t0 + stp) * 64 + lane);
        float4 g1 = __ldg(p4 + (size_t)(t0 + stp) * 64 + lane + 32);

        for (int t = t0; fwd ? (t < TM) : (t >= TM); t += stp) {
            int t2 = t + 2 * stp;
            float4 h0, h1;
            bool okp = fwd ? (t2 < TM) : (t2 >= TM);
            if (okp) {
                h0 = __ldg(p4 + (size_t)t2 * 64 + lane);
                h1 = __ldg(p4 + (size_t)t2 * 64 + lane + 32);
            }
            if (fwd) { if (t >= RSTG)          while (ld_acq_i(&s_tdF) + 13 < t) { } }
            else     { if (t <= Tt - 1 - RSTG) while (ld_acq_i(&s_tdB) - 13 > t) { } }

            float4* dst = (float4*)rbuf;
            dst[lane] = f0; dst[lane + 32] = f1;
            __syncwarp();

            float S = ex2f_(f0.x * INV_LN2) + ex2f_(f0.y * INV_LN2)
                    + ex2f_(f0.z * INV_LN2) + ex2f_(f0.w * INV_LN2)
                    + ex2f_(f1.x * INV_LN2) + ex2f_(f1.y * INV_LN2)
                    + ex2f_(f1.z * INV_LN2) + ex2f_(f1.w * INV_LN2);
#pragma unroll
            for (int o = 16; o; o >>= 1) S += __shfl_xor_sync(0xffffffffu, S, o);
            float l2 = lg2f_(S);

            float4 q;
            q.x = __fmaf_rn(rbuf[c0], INV_LN2, -l2);
            q.y = __fmaf_rn(rbuf[c1], INV_LN2, -l2);
            q.z = __fmaf_rn(rbuf[c2], INV_LN2, -l2);
            q.w = __fmaf_rn(rbuf[c3], INV_LN2, -l2);
            float* grow = fwd ? glpF[t & (RSTG - 1)] : glpB[t & (RSTG - 1)];
            ((float4*)grow)[lane] = q;
            __syncwarp();
            if (lane == 0)
                st_rel_f(&s_lpb[t], __fmaf_rn(f0.x, INV_LN2, -l2));

            f0 = g0; f1 = g1; g0 = h0; g1 = h1;
        }
        return;
    }

    if (grp == 0) {
        // ======================= forward (double-stepped) =======================
        const int i = tid;
        const int im1 = (i > 0) ? (i - 1) : 0;
        int tg_i  = s_tg[i];
        int tg_m  = (i > 0) ? s_tg[i - 1] : 0;
        int tg_m2 = (i > 1) ? s_tg[i - 2] : 0;
        const bool sk   = tg_i && (tg_i != tg_m);      // pair i
        const bool skm  = tg_m && (tg_m != tg_m2);     // pair i-1
        const bool tail = (i == 127);

        // alpha_0 into As[0]
        float lpB0 = pollf(&s_lpb[0]);
        float lpL0 = glpF[0][0];
        ((float2*)&As[0][4])[i] = (i == 0) ? make_float2(lpB0, lpL0)
                                           : make_float2(NEGV, NEGV);
        float a256 = NEGV;

        // single step alpha_0 -> alpha_1 (store As[1])
        {
            float lpBs = pollf(&s_lpb[1]);
            float lpLs = glpF[1][i];
            BARF();   // alpha_0 visible
            const float2* src = (const float2*)&As[0][0];
            float2 w1 = src[i + 1];   // s = 2i-2, 2i-1
            float2 w2 = src[i + 2];   // s = 2i,   2i+1
            float2 r = fpair(w1.y, w2.x, w2.y, sk, lpBs, lpLs);
            ((float2*)&As[1][4])[i] = r;
            if (tail) {
                float mT = fmaxf(a256, w2.y);
                a256 = fmaxf(mT + lg2f_(ex2f_(a256 - mT) + ex2f_(w2.y - mT)) + lpBs, NEGV);
            }
        }
        // prefetch for first double step (t=3: needs lp at 2 and 3)
        float lpB1 = pollf(&s_lpb[2]);
        float lpL1m = glpF[2][im1];
        float lpL1  = glpF[2][i];
        float lpB2 = pollf(&s_lpb[3]);
        float lpL2  = glpF[3][i];
        if (tid == 0) st_rel_i(&s_tdF, 1);
        BARF();

        int p = 1;
        for (int t = 3; t < TM; t += 2) {       // 255 double steps -> alpha_511
            const int c = p ^ 1;
            const float2* src = (const float2*)&As[p][0];
            float2 w0 = src[i];        // s = 2i-4, 2i-3
            float2 w1 = src[i + 1];    // s = 2i-2, 2i-1
            float2 w2 = src[i + 2];    // s = 2i,   2i+1

            // t-1: pairs i-1 and i (redundant halo)
            float2 u = fpair(w0.y, w1.x, w1.y, skm, lpB1, lpL1m);   // pair i-1
            float2 v = fpair(w1.y, w2.x, w2.y, sk,  lpB1, lpL1);    // pair i
            float a256m = a256;
            if (tail) {
                float mT = fmaxf(a256, w2.y);
                a256m = fmaxf(mT + lg2f_(ex2f_(a256 - mT) + ex2f_(w2.y - mT)) + lpB1, NEGV);
            }
            // t: pair i
            float2 r = fpair(u.y, v.x, v.y, sk, lpB2, lpL2);
            ((float2*)&As[c][4])[i] = r;
            if (tail) {
                float mT = fmaxf(a256m, v.y);
                a256 = fmaxf(mT + lg2f_(ex2f_(a256m - mT) + ex2f_(v.y - mT)) + lpB2, NEGV);
            }
            p = c;

            // prefetch next double step (t+1, t+2)
            int tn1 = (t + 1 < TM) ? (t + 1) : (TM - 1);
            int tn2 = (t + 2 < TM) ? (t + 2) : (TM - 1);
            lpB1  = pollf(&s_lpb[tn1]);
            lpL1m = glpF[tn1 & (RSTG - 1)][im1];
            lpL1  = glpF[tn1 & (RSTG - 1)][i];
            lpB2  = pollf(&s_lpb[tn2]);
            lpL2  = glpF[tn2 & (RSTG - 1)][i];
            if (tid == 0) st_rel_i(&s_tdF, t);
            BARF();
        }
        // alpha_511 in As[0] (p toggled 255 times from 1)

        BARC();   // beta~_512 ready in Bs[1]

        // ---- combine: emission-free transition + dot + lse over s ----
        {
            const float2* src = (const float2*)&As[0][0];
            float2 w1 = src[i + 1];
            float2 w2 = src[i + 2];
            float aEm1 = w1.y, aE0 = w2.x, aO0 = w2.y;
            float2 B2 = ((const float2*)&Bs[1][4])[i];

            float m  = fmaxf(fmaxf(aE0, aEm1), aO0);
            float e0 = ex2f_(aE0 - m), e1 = ex2f_(aEm1 - m), e2 = ex2f_(aO0 - m);
            float vE = m + lg2f_(e0 + e1)                   + B2.x;
            float vO = m + lg2f_(e2 + e0 + (sk ? e1 : 0.f)) + B2.y;

            float M = fmaxf(vE, vO);
            float E = ex2f_(vE - M) + ex2f_(vO - M);
            if (tail) {
                float mT = fmaxf(a256, aO0);
                float v256 = mT + lg2f_(ex2f_(a256 - mT) + ex2f_(aO0 - mT)) + Bs[1][260];
                float nm = fmaxf(M, v256);
                E = E * ex2f_(M - nm) + ex2f_(v256 - nm);
                M = nm;
            }
#pragma unroll
            for (int o = 16; o; o >>= 1) {
                float om = __shfl_xor_sync(0xffffffffu, M, o);
                float oe = __shfl_xor_sync(0xffffffffu, E, o);
                float nm = fmaxf(M, om);
                E = E * ex2f_(M - nm) + oe * ex2f_(om - nm);
                M = nm;
            }
            if (lane == 0) { red[2 * wid] = M; red[2 * wid + 1] = E; }
            BARF();
            if (tid == 0) {
                float Mf = red[0], Ef = red[1];
#pragma unroll
                for (int wv = 1; wv < 4; ++wv) {
                    float om = red[2 * wv], oe = red[2 * wv + 1];
                    float nm = fmaxf(Mf, om);
                    Ef = Ef * ex2f_(Mf - nm) + oe * ex2f_(om - nm);
                    Mf = nm;
                }
                float fin  = (Mf + lg2f_(Ef)) * LN2;
                float loss = (fin < -1e29f) ? 0.0f : -fin;
                int tld = (tl > 0) ? tl : 1;
                g_losses[n] = loss / (float)tld;
            }
        }
        return;
    }

    // ======================= backward (double-stepped) =======================
    {
        const int j   = tid - 128;
        const int jp1 = (j < 127) ? (j + 1) : 127;
        int tgj  = s_tg[j];
        int tgj1 = (j + 1 < Ll) ? s_tg[j + 1] : 0;
        int tgj2 = (j + 2 < Ll) ? s_tg[j + 2] : 0;
        const bool skb  = tgj1 && (tgj1 != tgj);       // pair j
        const bool skb1 = tgj2 && (tgj2 != tgj1);      // pair j+1
        const bool tail = (j == 127);

        // beta_1023 into Bs[1]
        float lpB0 = pollf(&s_lpb[Tt - 1]);
        float lpO0 = glpB[(Tt - 1) & (RSTG - 1)][j];
        {
            float2 b;
            b.x = (j == tl)     ? lpB0 : NEGV;
            b.y = (j == tl - 1) ? lpO0 : NEGV;
            ((float2*)&Bs[1][4])[j] = b;
            if (tail) Bs[1][260] = (tl == Ll || tl == 0) ? lpB0 : NEGV;
        }

        // single step beta_1023 -> beta_1022 (store Bs[0])
        {
            float lpBs = pollf(&s_lpb[Tt - 2]);
            float lpLs = glpB[(Tt - 2) & (RSTG - 1)][j];
            BARB();   // beta_1023 visible
            const float2* src = (const float2*)&Bs[1][0];
            float2 w0 = src[j + 2];   // s = 2j,   2j+1
            float2 w1 = src[j + 3];   // s = 2j+2, 2j+3  (j=127: (b256, NEGV))
            float2 r = bpair(w0.x, w0.y, w1.x, w1.y, skb, lpBs, lpLs);
            ((float2*)&Bs[0][4])[j] = r;
            if (tail) Bs[0][260] = fmaxf(Bs[1][260] + lpBs, NEGV);
        }
        float lpB1 = pollf(&s_lpb[Tt - 3]);
        float lpL1  = glpB[(Tt - 3) & (RSTG - 1)][j];
        float lpL1p = glpB[(Tt - 3) & (RSTG - 1)][jp1];
        float lpB2 = pollf(&s_lpb[Tt - 4]);
        float lpL2  = glpB[(Tt - 4) & (RSTG - 1)][j];
        if (tid == 128) st_rel_i(&s_tdB, Tt - 2);
        BARB();

        int p = 0;
        for (int t = Tt - 4; t >= TM; t -= 2) {   // 255 double steps -> beta_512
            const int c = p ^ 1;
            const float2* src = (const float2*)&Bs[p][0];
            float2 w0 = src[j + 2];    // s = 2j,   2j+1
            float2 w1 = src[j + 3];    // s = 2j+2, 2j+3
            float2 w2 = src[j + 4];    // s = 2j+4, 2j+5

            // t+1: pairs j and j+1 (redundant halo)
            float2 u = bpair(w0.x, w0.y, w1.x, w1.y, skb,  lpB1, lpL1);   // pair j
            float2 v = bpair(w1.x, w1.y, w2.x, w2.y, skb1, lpB1, lpL1p); // pair j+1
            // t: pair j
            float2 r = bpair(u.x, u.y, v.x, v.y, skb, lpB2, lpL2);
            ((float2*)&Bs[c][4])[j] = r;
            if (tail) Bs[c][260] = fmaxf(Bs[p][260] + lpB1 + lpB2, NEGV);
            p = c;

            int tn1 = (t - 1 >= TM) ? (t - 1) : TM;
            int tn2 = (t - 2 >= TM) ? (t - 2) : TM;
            lpB1  = pollf(&s_lpb[tn1]);
            lpL1  = glpB[tn1 & (RSTG - 1)][j];
            lpL1p = glpB[tn1 & (RSTG - 1)][jp1];
            lpB2  = pollf(&s_lpb[tn2]);
            lpL2  = glpB[tn2 & (RSTG - 1)][j];
            if (tid == 128) st_rel_i(&s_tdB, t);
            BARB();
        }
        // beta_512 in Bs[1]
        BARC();
        return;
    }
}

// ---------------------------------------------------------------------------
__global__ void __launch_bounds__(128) reduce_kernel(float* __restrict__ out) {
    int tid = threadIdx.x;
    float v = g_losses[tid];
#pragma unroll
    for (int o = 16; o; o >>= 1) v += __shfl_xor_sync(0xffffffffu, v, o);
    __shared__ float sm[4];
    if ((tid & 31) == 0) sm[tid >> 5] = v;
    __syncthreads();
    if (tid == 0) out[0] = (sm[0] + sm[1] + sm[2] + sm[3]) * (1.0f / (float)Nn);
}

// ---------------------------------------------------------------------------
extern "C" void kernel_launch(void* const* d_in, const int* in_sizes, int n_in,
                              void* d_out, int out_size) {
    const float* preds;
    const int*   targets;
    if (in_sizes[0] == Nn * Tt * Cc) {
        preds   = (const float*)d_in[0];
        targets = (const int*)  d_in[1];
    } else {
        preds   = (const float*)d_in[1];
        targets = (const int*)  d_in[0];
    }
    float* out = (float*)d_out;

    ctc_fused   <<<Nn, 512>>>(preds, targets);
    reduce_kernel<<<1, 128>>>(out);
}